// round 14
// baseline (speedup 1.0000x reference)
#include <cuda_runtime.h>
#include <cstdint>

// ---------------------------------------------------------------------------
// TTLinear: y[4096,4096] = x[4096,1024] @ W[1024,4096] + bias
// mma.sync tf32 path (tcgen05 rejected by this harness's ptxas target).
//
// R14 == R13 resubmission (R13 died with an opaque "container failed twice";
// kernel re-audited clean — pipeline/wait-group math, smem budgets, bounds).
//  * GEMM: 256x128 CTA tile, 256 threads (4Mx2N warps of 64x64) -> L2->SM
//    operand traffic 1074MB -> 805MB. Same 3-stage / 1-sync pipeline.
//  * k_g3 + k_wt fused into k_g3wt (one block per N3; G3 slice lives in
//    smem) -> kills the 8MB g_G3 intermediate entirely.
// Arithmetic per output unchanged -> rel_err must stay 2.9266e-4.
// ---------------------------------------------------------------------------

#define TOKENS 4096
#define KDIM   1024
#define NDIM   4096

__device__ float g_G2[64 * 64 * 16];              // 256 KB [M2][N2][r2]
__device__ float g_Wt[(size_t)NDIM * KDIM];       // 16 MB, [N][K], k-permuted, tf32
__device__ float g_Xr[(size_t)TOKENS * KDIM];     // 16 MB, [M][K], k-permuted, tf32

__device__ __forceinline__ uint32_t f2tf32(float f) {
    uint32_t u; asm("cvt.rna.tf32.f32 %0, %1;" : "=r"(u) : "f"(f)); return u;
}

// ---------------- builders ----------------

// x -> tf32, k-permuted within each 8-group: new order (0,4,1,5,2,6,3,7)
__global__ void k_x(const float* __restrict__ x) {
    int g = blockIdx.x * 256 + threadIdx.x;            // 524288 8-float groups
    const float4* src = reinterpret_cast<const float4*>(x) + 2 * (size_t)g;
    float4 v0 = src[0], v1 = src[1];
    float4 p0, p1;
    p0.x = __uint_as_float(f2tf32(v0.x)); p0.y = __uint_as_float(f2tf32(v1.x));
    p0.z = __uint_as_float(f2tf32(v0.y)); p0.w = __uint_as_float(f2tf32(v1.y));
    p1.x = __uint_as_float(f2tf32(v0.z)); p1.y = __uint_as_float(f2tf32(v1.z));
    p1.z = __uint_as_float(f2tf32(v0.w)); p1.w = __uint_as_float(f2tf32(v1.w));
    float4* dst = reinterpret_cast<float4*>(g_Xr) + 2 * (size_t)g;
    dst[0] = p0; dst[1] = p1;
}

__global__ void k_g2(const float* __restrict__ c0, const float* __restrict__ c1) {
    int idx = blockIdx.x * 256 + threadIdx.x;          // 65536
    int r2 = idx & 15;
    int N2 = (idx >> 4) & 63;
    int M2 = idx >> 10;
    int m1 = M2 >> 3, m2 = M2 & 7, n1 = N2 >> 3, n2 = N2 & 7;
    float s = 0.f;
#pragma unroll
    for (int r1 = 0; r1 < 16; r1++)
        s += c0[(m1 * 8 + n1) * 16 + r1] * c1[((r1 * 8 + m2) * 8 + n2) * 16 + r2];
    g_G2[idx] = s;
}

// Fused G3 + W^T builder. One block per N3 (=512 blocks, 256 threads).
// Computes the G3[:,N3,:] slice in smem (stride-17 padded), then the 8
// out-feature rows N3*8+n4 of g_Wt, k-permuted:
//   col = (M3>>1)*8 + 2*m4 + (M3&1),  M3 = 2g+h.
// Summation order identical to the unfused k_g3/k_wt -> bit-identical W.
#define G3S 17
__global__ void __launch_bounds__(256)
k_g3wt(const float* __restrict__ c2, const float* __restrict__ c3) {
    __shared__ float sG2[64 * 16];        // [M2][r2]        (slice at N2)
    __shared__ float sc2[16 * 4 * 16];    // [r2][m3][r3]    (slice at n3)
    __shared__ float sc3[512];
    __shared__ float sG3[256 * G3S];      // [M3][r3] padded

    const int t  = threadIdx.x;
    const int N3 = blockIdx.x;            // 0..511
    const int N2 = N3 >> 3, n3 = N3 & 7;

    for (int i = t; i < 1024; i += 256) {
        int M2 = i >> 4, r2 = i & 15;
        sG2[i] = g_G2[(M2 * 64 + N2) * 16 + r2];
    }
    for (int i = t; i < 1024; i += 256) {
        int r2 = i >> 6, m3 = (i >> 4) & 3, r3 = i & 15;
        sc2[i] = c2[((r2 * 4 + m3) * 8 + n3) * 16 + r3];
    }
    sc3[t] = c3[t];
    sc3[t + 256] = c3[t + 256];
    __syncthreads();

    // G3 slice: 256 M3 x 16 r3
    for (int i = t; i < 4096; i += 256) {
        int M3 = i >> 4, r3 = i & 15;
        int M2 = M3 >> 2, m3 = M3 & 3;
        float s = 0.f;
#pragma unroll
        for (int r2 = 0; r2 < 16; r2++)
            s += sG2[M2 * 16 + r2] * sc2[(r2 * 4 + m3) * 16 + r3];
        sG3[M3 * G3S + r3] = s;
    }
    __syncthreads();

    // W rows: thread -> (n4 half np2, k-group g); 4 n4 rows per thread
    const int g = t & 127, np2 = t >> 7;
    float outv[4][8];                     // [q][permuted 8 floats]
#pragma unroll
    for (int h = 0; h < 2; h++) {
        int M3 = 2 * g + h;
        float g3[16];
#pragma unroll
        for (int r3 = 0; r3 < 16; r3++)
            g3[r3] = sG3[M3 * G3S + r3];
#pragma unroll
        for (int q = 0; q < 4; q++) {
            int n4 = np2 * 4 + q;
            float acc[4] = {0.f, 0.f, 0.f, 0.f};
#pragma unroll
            for (int r3 = 0; r3 < 16; r3++) {
                float gg = g3[r3];
#pragma unroll
                for (int m4 = 0; m4 < 4; m4++)
                    acc[m4] += gg * sc3[(r3 * 4 + m4) * 8 + n4];
            }
#pragma unroll
            for (int m4 = 0; m4 < 4; m4++)
                outv[q][2 * m4 + h] = __uint_as_float(f2tf32(acc[m4]));
        }
    }
#pragma unroll
    for (int q = 0; q < 4; q++) {
        int o = N3 * 8 + np2 * 4 + q;
        float4* dst = reinterpret_cast<float4*>(&g_Wt[(size_t)o * KDIM + g * 8]);
        dst[0] = make_float4(outv[q][0], outv[q][1], outv[q][2], outv[q][3]);
        dst[1] = make_float4(outv[q][4], outv[q][5], outv[q][6], outv[q][7]);
    }
}

// ---------------- GEMM (mma.sync tf32, 256x128 tile, 3-stage) ---------------

#define BM 256
#define BN 128
#define BK 32
#define A_STAGE (BM * 32)            // 8192 floats = 32KB
#define B_STAGE (BN * 32)            // 4096 floats = 16KB
#define STAGE (A_STAGE + B_STAGE)    // 48KB
#define NSTG 3
#define SMEM_BYTES (NSTG * STAGE * 4)   // 147456

__device__ __forceinline__ void cp_async16(void* s, const void* g) {
    uint32_t sa = (uint32_t)__cvta_generic_to_shared(s);
    asm volatile("cp.async.cg.shared.global [%0], [%1], 16;\n" :: "r"(sa), "l"(g));
}

__device__ __forceinline__ void mma8(float d[4], const uint32_t a[4], const uint32_t b[2]) {
    asm volatile(
        "mma.sync.aligned.m16n8k8.row.col.f32.tf32.tf32.f32 "
        "{%0,%1,%2,%3}, {%4,%5,%6,%7}, {%8,%9}, {%0,%1,%2,%3};\n"
        : "+f"(d[0]), "+f"(d[1]), "+f"(d[2]), "+f"(d[3])
        : "r"(a[0]), "r"(a[1]), "r"(a[2]), "r"(a[3]), "r"(b[0]), "r"(b[1]));
}

__global__ void __launch_bounds__(256, 1)
gemm_kernel(const float* __restrict__ bias, float* __restrict__ out) {
    extern __shared__ float smem[];

    const int tid  = threadIdx.x;
    const int warp = tid >> 5, lane = tid & 31;
    const int wm = (warp >> 1) * 64;      // warp M offset (0/64/128/192)
    const int wn = (warp & 1) * 64;       // warp N offset (0/64)
    const int m0 = blockIdx.y * BM;
    const int n0 = blockIdx.x * BN;
    const int rl = lane >> 2;             // fragment row-in-group 0..7
    const int jl = lane & 3;

    float acc[4][8][4];                   // 64(M) x 64(N) per warp
#pragma unroll
    for (int i = 0; i < 4; i++)
#pragma unroll
        for (int j = 0; j < 8; j++)
#pragma unroll
            for (int k = 0; k < 4; k++) acc[i][j][k] = 0.f;

    // store: chunk ch (16B) of row r lands at chunk ch ^ ((r&3)<<1)
    auto load_stage = [&](int s, int k0) {
        float* A = smem + s * STAGE;
        float* B = A + A_STAGE;
#pragma unroll
        for (int i = 0; i < 8; i++) {     // A: 256 rows x 8 chunks
            int q = i * 256 + tid;
            int r = q >> 3, ch = q & 7;
            int sw = r * 32 + ((ch ^ ((r & 3) << 1)) << 2);
            cp_async16(&A[sw], &g_Xr[(size_t)(m0 + r) * KDIM + k0 + ch * 4]);
        }
#pragma unroll
        for (int i = 0; i < 4; i++) {     // B: 128 rows x 8 chunks
            int q = i * 256 + tid;
            int r = q >> 3, ch = q & 7;
            int sw = r * 32 + ((ch ^ ((r & 3) << 1)) << 2);
            cp_async16(&B[sw], &g_Wt[(size_t)(n0 + r) * KDIM + k0 + ch * 4]);
        }
    };

    load_stage(0, 0);
    asm volatile("cp.async.commit_group;\n" ::);
    load_stage(1, BK);
    asm volatile("cp.async.commit_group;\n" ::);

    const int NT = KDIM / BK;             // 32
    int s = 0, s2 = 2;                    // current slot, slot for kt+2
#pragma unroll 1
    for (int kt = 0; kt < NT; kt++) {
        if (kt < NT - 1)
            asm volatile("cp.async.wait_group 1;\n" ::);
        else
            asm volatile("cp.async.wait_group 0;\n" ::);
        __syncthreads();   // also releases slot s2 (== slot kt-1)

        const float* A = smem + s * STAGE;
        const float* B = A + A_STAGE;

#pragma unroll
        for (int ks = 0; ks < 4; ks++) {
            const int xpart = (((2 * ks + (jl >> 1)) ^ ((rl & 3) << 1)) << 2)
                              + 2 * (jl & 1);
            uint32_t af[4][4];
            const float* Ab0 = A + (wm + rl) * 32 + xpart;
#pragma unroll
            for (int mi = 0; mi < 4; mi++) {
                uint2 lo = *reinterpret_cast<const uint2*>(Ab0 + mi * 16 * 32);
                uint2 hi = *reinterpret_cast<const uint2*>(Ab0 + mi * 16 * 32 + 8 * 32);
                af[mi][0] = lo.x; af[mi][1] = hi.x; af[mi][2] = lo.y; af[mi][3] = hi.y;
            }
            uint32_t bf[8][2];
            const float* Bb0 = B + (wn + rl) * 32 + xpart;
#pragma unroll
            for (int ni = 0; ni < 8; ni++) {
                uint2 bb = *reinterpret_cast<const uint2*>(Bb0 + ni * 8 * 32);
                bf[ni][0] = bb.x; bf[ni][1] = bb.y;
            }
#pragma unroll
            for (int mi = 0; mi < 4; mi++)
#pragma unroll
                for (int ni = 0; ni < 8; ni++)
                    mma8(acc[mi][ni], af[mi], bf[ni]);
        }

        if (kt + 2 < NT) {
            load_stage(s2, (kt + 2) * BK);
            asm volatile("cp.async.commit_group;\n" ::);
        }
        s  = (s  == NSTG - 1) ? 0 : s + 1;
        s2 = (s2 == NSTG - 1) ? 0 : s2 + 1;
    }

    // epilogue: + bias, direct STG
#pragma unroll
    for (int mi = 0; mi < 4; mi++) {
        int row = m0 + wm + mi * 16 + rl;
#pragma unroll
        for (int ni = 0; ni < 8; ni++) {
            int col = n0 + wn + ni * 8 + 2 * jl;
            float b0 = bias[col], b1 = bias[col + 1];
            float2 v0 = make_float2(acc[mi][ni][0] + b0, acc[mi][ni][1] + b1);
            float2 v1 = make_float2(acc[mi][ni][2] + b0, acc[mi][ni][3] + b1);
            *reinterpret_cast<float2*>(&out[(size_t)row * NDIM + col]) = v0;
            *reinterpret_cast<float2*>(&out[(size_t)(row + 8) * NDIM + col]) = v1;
        }
    }
}

// ---------------- launch ----------------

extern "C" void kernel_launch(void* const* d_in, const int* in_sizes, int n_in,
                              void* d_out, int out_size) {
    const float* x     = (const float*)d_in[0];
    const float* core0 = (const float*)d_in[1];
    const float* core1 = (const float*)d_in[2];
    const float* core2 = (const float*)d_in[3];
    const float* core3 = (const float*)d_in[4];
    const float* bias  = (const float*)d_in[5];
    float* out = (float*)d_out;

    k_x    <<<2048, 256>>>(x);
    k_g2   <<<256, 256>>>(core0, core1);
    k_g3wt <<<512, 256>>>(core2, core3);

    cudaFuncSetAttribute(gemm_kernel,
                         cudaFuncAttributeMaxDynamicSharedMemorySize, SMEM_BYTES);
    gemm_kernel<<<dim3(NDIM / BN, TOKENS / BM), 256, SMEM_BYTES>>>(bias, out);
}

// round 16
// speedup vs baseline: 1.1604x; 1.1604x over previous
#include <cuda_runtime.h>
#include <cstdint>

// ---------------------------------------------------------------------------
// TTLinear: y[4096,4096] = x[4096,1024] @ W[1024,4096] + bias
// mma.sync tf32 path (tcgen05 rejected by this harness's ptxas target).
//
// R15 = best-of-both recombination:
//  * GEMM: exact R12 config (128x128 tile, 128 thr, 64x64 warp tiles, XOR
//    swizzle, 3-stage cp.async / 1 sync per tile, 2 CTAs/SM) — measured
//    ~160us. R14 proved 256x128 @ 1 CTA/SM loses to sync exposure despite
//    3x lower L2 traffic.
//  * Builders: R14's fused k_g3wt (no g_G3 global intermediate) — measured
//    ~24us total with k_x + k_g2.
// Arithmetic per output unchanged -> rel_err must stay 2.9266e-4.
// ---------------------------------------------------------------------------

#define TOKENS 4096
#define KDIM   1024
#define NDIM   4096

__device__ float g_G2[64 * 64 * 16];              // 256 KB [M2][N2][r2]
__device__ float g_Wt[(size_t)NDIM * KDIM];       // 16 MB, [N][K], k-permuted, tf32
__device__ float g_Xr[(size_t)TOKENS * KDIM];     // 16 MB, [M][K], k-permuted, tf32

__device__ __forceinline__ uint32_t f2tf32(float f) {
    uint32_t u; asm("cvt.rna.tf32.f32 %0, %1;" : "=r"(u) : "f"(f)); return u;
}

// ---------------- builders ----------------

// x -> tf32, k-permuted within each 8-group: new order (0,4,1,5,2,6,3,7)
__global__ void k_x(const float* __restrict__ x) {
    int g = blockIdx.x * 256 + threadIdx.x;            // 524288 8-float groups
    const float4* src = reinterpret_cast<const float4*>(x) + 2 * (size_t)g;
    float4 v0 = src[0], v1 = src[1];
    float4 p0, p1;
    p0.x = __uint_as_float(f2tf32(v0.x)); p0.y = __uint_as_float(f2tf32(v1.x));
    p0.z = __uint_as_float(f2tf32(v0.y)); p0.w = __uint_as_float(f2tf32(v1.y));
    p1.x = __uint_as_float(f2tf32(v0.z)); p1.y = __uint_as_float(f2tf32(v1.z));
    p1.z = __uint_as_float(f2tf32(v0.w)); p1.w = __uint_as_float(f2tf32(v1.w));
    float4* dst = reinterpret_cast<float4*>(g_Xr) + 2 * (size_t)g;
    dst[0] = p0; dst[1] = p1;
}

__global__ void k_g2(const float* __restrict__ c0, const float* __restrict__ c1) {
    int idx = blockIdx.x * 256 + threadIdx.x;          // 65536
    int r2 = idx & 15;
    int N2 = (idx >> 4) & 63;
    int M2 = idx >> 10;
    int m1 = M2 >> 3, m2 = M2 & 7, n1 = N2 >> 3, n2 = N2 & 7;
    float s = 0.f;
#pragma unroll
    for (int r1 = 0; r1 < 16; r1++)
        s += c0[(m1 * 8 + n1) * 16 + r1] * c1[((r1 * 8 + m2) * 8 + n2) * 16 + r2];
    g_G2[idx] = s;
}

// Fused G3 + W^T builder. One block per N3 (=512 blocks, 256 threads).
// Computes the G3[:,N3,:] slice in smem (stride-17 padded), then the 8
// out-feature rows N3*8+n4 of g_Wt, k-permuted:
//   col = (M3>>1)*8 + 2*m4 + (M3&1),  M3 = 2g+h.
// Summation order identical to the unfused k_g3/k_wt -> bit-identical W.
#define G3S 17
__global__ void __launch_bounds__(256)
k_g3wt(const float* __restrict__ c2, const float* __restrict__ c3) {
    __shared__ float sG2[64 * 16];        // [M2][r2]        (slice at N2)
    __shared__ float sc2[16 * 4 * 16];    // [r2][m3][r3]    (slice at n3)
    __shared__ float sc3[512];
    __shared__ float sG3[256 * G3S];      // [M3][r3] padded

    const int t  = threadIdx.x;
    const int N3 = blockIdx.x;            // 0..511
    const int N2 = N3 >> 3, n3 = N3 & 7;

    for (int i = t; i < 1024; i += 256) {
        int M2 = i >> 4, r2 = i & 15;
        sG2[i] = g_G2[(M2 * 64 + N2) * 16 + r2];
    }
    for (int i = t; i < 1024; i += 256) {
        int r2 = i >> 6, m3 = (i >> 4) & 3, r3 = i & 15;
        sc2[i] = c2[((r2 * 4 + m3) * 8 + n3) * 16 + r3];
    }
    sc3[t] = c3[t];
    sc3[t + 256] = c3[t + 256];
    __syncthreads();

    // G3 slice: 256 M3 x 16 r3
    for (int i = t; i < 4096; i += 256) {
        int M3 = i >> 4, r3 = i & 15;
        int M2 = M3 >> 2, m3 = M3 & 3;
        float s = 0.f;
#pragma unroll
        for (int r2 = 0; r2 < 16; r2++)
            s += sG2[M2 * 16 + r2] * sc2[(r2 * 4 + m3) * 16 + r3];
        sG3[M3 * G3S + r3] = s;
    }
    __syncthreads();

    // W rows: thread -> (n4 half np2, k-group g); 4 n4 rows per thread
    const int g = t & 127, np2 = t >> 7;
    float outv[4][8];                     // [q][permuted 8 floats]
#pragma unroll
    for (int h = 0; h < 2; h++) {
        int M3 = 2 * g + h;
        float g3[16];
#pragma unroll
        for (int r3 = 0; r3 < 16; r3++)
            g3[r3] = sG3[M3 * G3S + r3];
#pragma unroll
        for (int q = 0; q < 4; q++) {
            int n4 = np2 * 4 + q;
            float acc[4] = {0.f, 0.f, 0.f, 0.f};
#pragma unroll
            for (int r3 = 0; r3 < 16; r3++) {
                float gg = g3[r3];
#pragma unroll
                for (int m4 = 0; m4 < 4; m4++)
                    acc[m4] += gg * sc3[(r3 * 4 + m4) * 8 + n4];
            }
#pragma unroll
            for (int m4 = 0; m4 < 4; m4++)
                outv[q][2 * m4 + h] = __uint_as_float(f2tf32(acc[m4]));
        }
    }
#pragma unroll
    for (int q = 0; q < 4; q++) {
        int o = N3 * 8 + np2 * 4 + q;
        float4* dst = reinterpret_cast<float4*>(&g_Wt[(size_t)o * KDIM + g * 8]);
        dst[0] = make_float4(outv[q][0], outv[q][1], outv[q][2], outv[q][3]);
        dst[1] = make_float4(outv[q][4], outv[q][5], outv[q][6], outv[q][7]);
    }
}

// ---------------- GEMM (mma.sync tf32, 128x128, 3-stage, 1 sync/tile) -------

#define BM 128
#define BN 128
#define BK 32
#define A_STAGE (BM * 32)            // 4096 floats = 16KB
#define B_STAGE (BN * 32)
#define STAGE (A_STAGE + B_STAGE)    // 32KB
#define NSTG 3
#define SMEM_BYTES (NSTG * STAGE * 4)   // 98304 -> 2 CTAs/SM

__device__ __forceinline__ void cp_async16(void* s, const void* g) {
    uint32_t sa = (uint32_t)__cvta_generic_to_shared(s);
    asm volatile("cp.async.cg.shared.global [%0], [%1], 16;\n" :: "r"(sa), "l"(g));
}

__device__ __forceinline__ void mma8(float d[4], const uint32_t a[4], const uint32_t b[2]) {
    asm volatile(
        "mma.sync.aligned.m16n8k8.row.col.f32.tf32.tf32.f32 "
        "{%0,%1,%2,%3}, {%4,%5,%6,%7}, {%8,%9}, {%0,%1,%2,%3};\n"
        : "+f"(d[0]), "+f"(d[1]), "+f"(d[2]), "+f"(d[3])
        : "r"(a[0]), "r"(a[1]), "r"(a[2]), "r"(a[3]), "r"(b[0]), "r"(b[1]));
}

__global__ void __launch_bounds__(128, 2)
gemm_kernel(const float* __restrict__ bias, float* __restrict__ out) {
    extern __shared__ float smem[];

    const int tid  = threadIdx.x;
    const int warp = tid >> 5, lane = tid & 31;
    const int wm = (warp >> 1) * 64;      // warp M offset (0/64)
    const int wn = (warp & 1) * 64;       // warp N offset (0/64)
    const int m0 = blockIdx.y * BM;
    const int n0 = blockIdx.x * BN;
    const int rl = lane >> 2;             // fragment row-in-group 0..7
    const int jl = lane & 3;

    float acc[4][8][4];                   // 64(M) x 64(N) per warp
#pragma unroll
    for (int i = 0; i < 4; i++)
#pragma unroll
        for (int j = 0; j < 8; j++)
#pragma unroll
            for (int k = 0; k < 4; k++) acc[i][j][k] = 0.f;

    // store: chunk ch (16B) of row r lands at chunk ch ^ ((r&3)<<1)
    auto load_stage = [&](int s, int k0) {
        float* A = smem + s * STAGE;
        float* B = A + A_STAGE;
#pragma unroll
        for (int i = 0; i < 8; i++) {
            int q = i * 128 + tid;
            int r = q >> 3, ch = q & 7;
            int sw = r * 32 + ((ch ^ ((r & 3) << 1)) << 2);
            cp_async16(&A[sw], &g_Xr[(size_t)(m0 + r) * KDIM + k0 + ch * 4]);
        }
#pragma unroll
        for (int i = 0; i < 8; i++) {
            int q = i * 128 + tid;
            int r = q >> 3, ch = q & 7;
            int sw = r * 32 + ((ch ^ ((r & 3) << 1)) << 2);
            cp_async16(&B[sw], &g_Wt[(size_t)(n0 + r) * KDIM + k0 + ch * 4]);
        }
    };

    load_stage(0, 0);
    asm volatile("cp.async.commit_group;\n" ::);
    load_stage(1, BK);
    asm volatile("cp.async.commit_group;\n" ::);

    const int NT = KDIM / BK;             // 32
    int s = 0, s2 = 2;                    // current slot, slot for kt+2
#pragma unroll 1
    for (int kt = 0; kt < NT; kt++) {
        if (kt < NT - 1)
            asm volatile("cp.async.wait_group 1;\n" ::);
        else
            asm volatile("cp.async.wait_group 0;\n" ::);
        __syncthreads();   // also releases slot s2 (== slot kt-1)

        const float* A = smem + s * STAGE;
        const float* B = A + A_STAGE;

#pragma unroll
        for (int ks = 0; ks < 4; ks++) {
            const int xpart = (((2 * ks + (jl >> 1)) ^ ((rl & 3) << 1)) << 2)
                              + 2 * (jl & 1);
            uint32_t af[4][4];
            const float* Ab0 = A + (wm + rl) * 32 + xpart;
#pragma unroll
            for (int mi = 0; mi < 4; mi++) {
                uint2 lo = *reinterpret_cast<const uint2*>(Ab0 + mi * 16 * 32);
                uint2 hi = *reinterpret_cast<const uint2*>(Ab0 + mi * 16 * 32 + 8 * 32);
                af[mi][0] = lo.x; af[mi][1] = hi.x; af[mi][2] = lo.y; af[mi][3] = hi.y;
            }
            uint32_t bf[8][2];
            const float* Bb0 = B + (wn + rl) * 32 + xpart;
#pragma unroll
            for (int ni = 0; ni < 8; ni++) {
                uint2 bb = *reinterpret_cast<const uint2*>(Bb0 + ni * 8 * 32);
                bf[ni][0] = bb.x; bf[ni][1] = bb.y;
            }
#pragma unroll
            for (int mi = 0; mi < 4; mi++)
#pragma unroll
                for (int ni = 0; ni < 8; ni++)
                    mma8(acc[mi][ni], af[mi], bf[ni]);
        }

        if (kt + 2 < NT) {
            load_stage(s2, (kt + 2) * BK);
            asm volatile("cp.async.commit_group;\n" ::);
        }
        s  = (s  == NSTG - 1) ? 0 : s + 1;
        s2 = (s2 == NSTG - 1) ? 0 : s2 + 1;
    }

    // epilogue: + bias, direct STG
#pragma unroll
    for (int mi = 0; mi < 4; mi++) {
        int row = m0 + wm + mi * 16 + rl;
#pragma unroll
        for (int ni = 0; ni < 8; ni++) {
            int col = n0 + wn + ni * 8 + 2 * jl;
            float b0 = bias[col], b1 = bias[col + 1];
            float2 v0 = make_float2(acc[mi][ni][0] + b0, acc[mi][ni][1] + b1);
            float2 v1 = make_float2(acc[mi][ni][2] + b0, acc[mi][ni][3] + b1);
            *reinterpret_cast<float2*>(&out[(size_t)row * NDIM + col]) = v0;
            *reinterpret_cast<float2*>(&out[(size_t)(row + 8) * NDIM + col]) = v1;
        }
    }
}

// ---------------- launch ----------------

extern "C" void kernel_launch(void* const* d_in, const int* in_sizes, int n_in,
                              void* d_out, int out_size) {
    const float* x     = (const float*)d_in[0];
    const float* core0 = (const float*)d_in[1];
    const float* core1 = (const float*)d_in[2];
    const float* core2 = (const float*)d_in[3];
    const float* core3 = (const float*)d_in[4];
    const float* bias  = (const float*)d_in[5];
    float* out = (float*)d_out;

    k_x    <<<2048, 256>>>(x);
    k_g2   <<<256, 256>>>(core0, core1);
    k_g3wt <<<512, 256>>>(core2, core3);

    cudaFuncSetAttribute(gemm_kernel,
                         cudaFuncAttributeMaxDynamicSharedMemorySize, SMEM_BYTES);
    gemm_kernel<<<dim3(NDIM / BN, TOKENS / BM), 128, SMEM_BYTES>>>(bias, out);
}